// round 9
// baseline (speedup 1.0000x reference)
#include <cuda_runtime.h>
#include <cstdint>

// out = -weight * sum_{k=0}^{M-1} f[k]*f[k+D] / (N-1),  M = (N-1)*D, D=2000.
//
// TMA (cp.async.bulk) + mbarrier pipeline, 1 CTA/SM:
//   - 152 blocks x 256 threads, 5-stage ring of 40KB smem tiles
//     (32KB payload + 8KB halo so every b-read f[k+D] is in-tile).
//   - thread 0 = embedded producer: steals 32KB chunks via atomicAdd and
//     issues cp.async.bulk into the ring; DRAM request stream is decoupled
//     from consumer FFMA progress (no more per-chunk pipeline drains).
//   - consumers compute from smem; per-thread register accumulator across
//     all tiles; one block reduce at the end + last-block final reduce.
//   - exhaustion signaled by meta[slot] = 0.

#define NBLOCKS 152
#define NTHREADS 256
#define NSTAGES 5
#define STEP_F4 2048                 // 32KB payload per tile (float4)
#define TILE_F4 2560                 // 40KB tile incl. 512-f4 halo (>= Dv=500)
#define TILE_BYTES (TILE_F4 * 16)
#define SMEM_DATA_OFF 1024
#define SMEM_SZ (SMEM_DATA_OFF + NSTAGES * TILE_BYTES)

__device__ float g_partials[NBLOCKS];
__device__ unsigned int g_next = 0;
__device__ unsigned int g_done = 0;

__device__ __forceinline__ uint32_t smem_u32(const void* p) {
    uint32_t a;
    asm("{ .reg .u64 t; cvta.to.shared.u64 t, %1; cvt.u32.u64 %0, t; }"
        : "=r"(a) : "l"(p));
    return a;
}

#define MBAR_INIT(addr, cnt) \
    asm volatile("mbarrier.init.shared.b64 [%0], %1;" :: "r"(addr), "r"(cnt) : "memory")
#define MBAR_EXPECT_TX(addr, bytes) \
    asm volatile("mbarrier.arrive.expect_tx.shared.b64 _, [%0], %1;" \
                 :: "r"(addr), "r"(bytes) : "memory")
#define MBAR_ARRIVE(addr) \
    asm volatile("mbarrier.arrive.shared.b64 _, [%0];" :: "r"(addr) : "memory")
#define MBAR_WAIT(addr, phase) do {                                          \
    uint32_t _m = (addr), _p = (phase), _ok;                                 \
    asm volatile("{\n\t.reg .pred p;\n\t"                                    \
        "mbarrier.try_wait.parity.acquire.cta.shared::cta.b64 p, [%1], %2;\n\t" \
        "selp.b32 %0, 1, 0, p;\n\t}"                                         \
        : "=r"(_ok) : "r"(_m), "r"(_p) : "memory");                          \
    if (!_ok) {                                                              \
        asm volatile("{\n\t.reg .pred P1;\n\t"                               \
            "WL_%=:\n\t"                                                     \
            "mbarrier.try_wait.parity.acquire.cta.shared::cta.b64 P1, [%0], %1, 0x989680;\n\t" \
            "@P1 bra.uni WD_%=;\n\t"                                         \
            "bra.uni WL_%=;\n\t"                                             \
            "WD_%=:\n\t}" :: "r"(_m), "r"(_p) : "memory");                   \
    }                                                                        \
} while (0)

__global__ __launch_bounds__(NTHREADS, 1)
void shifted_dot_tma(const float4* __restrict__ in4, long long Mv,
                     long long Nf4, int Dv, int nchunks,
                     const float* __restrict__ weight, float* __restrict__ out,
                     float inv_nm1) {
    extern __shared__ char smem[];
    float4* tiles = (float4*)(smem + SMEM_DATA_OFF);
    volatile int* meta = (volatile int*)(smem + 128);
    const uint32_t base = smem_u32(smem);
    const uint32_t full0 = base;        // 5 x 8B mbarriers
    const uint32_t empty0 = base + 64;  // 5 x 8B mbarriers
    const int tid = threadIdx.x;

    if (tid == 0) {
        #pragma unroll
        for (int s = 0; s < NSTAGES; s++) {
            MBAR_INIT(full0 + 8u * s, 1);
            MBAR_INIT(empty0 + 8u * s, NTHREADS);
        }
    }
    __syncthreads();

    // producer state (thread 0 only)
    int p_slot = 0, p_phase = 1;       // phase=1: first empty-waits pass
    bool p_stop = false;

    // one producer step: steal a chunk, issue bulk copy into p_slot
    auto producer_step = [&]() {
        MBAR_WAIT(empty0 + 8u * p_slot, (uint32_t)p_phase);
        unsigned int c = atomicAdd(&g_next, 1u);
        if (c < (unsigned int)nchunks) {
            long long beg = (long long)c * STEP_F4;
            long long rem = Mv - beg;
            int len = rem < STEP_F4 ? (int)rem : STEP_F4;
            long long avail = Nf4 - beg;
            unsigned int bytes =
                (unsigned int)((avail < TILE_F4 ? avail : (long long)TILE_F4) * 16);
            meta[p_slot] = len;
            MBAR_EXPECT_TX(full0 + 8u * p_slot, bytes);
            uint32_t dst = base + SMEM_DATA_OFF + (uint32_t)p_slot * TILE_BYTES;
            const char* src = (const char*)in4 + beg * 16;
            asm volatile(
                "cp.async.bulk.shared::cta.global.mbarrier::complete_tx::bytes "
                "[%0], [%1], %2, [%3];"
                :: "r"(dst), "l"(src), "r"(bytes), "r"(full0 + 8u * p_slot)
                : "memory");
        } else {
            meta[p_slot] = 0;           // terminate marker
            MBAR_ARRIVE(full0 + 8u * p_slot);  // release: meta visible
            p_stop = true;
        }
        if (++p_slot == NSTAGES) { p_slot = 0; p_phase ^= 1; }
    };

    // prologue: fill NSTAGES-1 stages ahead
    if (tid == 0) {
        #pragma unroll
        for (int k = 0; k < NSTAGES - 1; k++)
            if (!p_stop) producer_step();
    }

    float acc = 0.0f;
    int c_slot = 0, c_phase = 0;

    for (;;) {
        if (tid == 0 && !p_stop) producer_step();

        MBAR_WAIT(full0 + 8u * c_slot, (uint32_t)c_phase);
        int len = meta[c_slot];
        if (len == 0) break;

        const float4* tile = tiles + c_slot * TILE_F4;
        if (len == STEP_F4) {
            #pragma unroll
            for (int u = 0; u < STEP_F4 / NTHREADS; u++) {
                int i = tid + u * NTHREADS;
                float4 a = tile[i];
                float4 b = tile[i + Dv];
                acc += a.x * b.x + a.y * b.y + a.z * b.z + a.w * b.w;
            }
        } else {
            for (int i = tid; i < len; i += NTHREADS) {
                float4 a = tile[i];
                float4 b = tile[i + Dv];
                acc += a.x * b.x + a.y * b.y + a.z * b.z + a.w * b.w;
            }
        }
        MBAR_ARRIVE(empty0 + 8u * c_slot);   // release: reads done
        if (++c_slot == NSTAGES) { c_slot = 0; c_phase ^= 1; }
    }

    // block reduce
    #pragma unroll
    for (int o = 16; o > 0; o >>= 1)
        acc += __shfl_xor_sync(0xffffffff, acc, o);

    __shared__ float s[NTHREADS / 32];
    if ((tid & 31) == 0) s[tid >> 5] = acc;
    __syncthreads();

    __shared__ bool is_last;
    if (tid == 0) {
        float v = 0.0f;
        #pragma unroll
        for (int i = 0; i < NTHREADS / 32; i++) v += s[i];
        g_partials[blockIdx.x] = v;
        __threadfence();
        unsigned int old = atomicAdd(&g_done, 1u);
        is_last = (old == gridDim.x - 1);
    }
    __syncthreads();

    if (is_last) {
        const volatile float* p = g_partials;
        float v = 0.0f;
        for (int i = tid; i < (int)gridDim.x; i += NTHREADS) v += p[i];
        #pragma unroll
        for (int o = 16; o > 0; o >>= 1)
            v += __shfl_xor_sync(0xffffffff, v, o);
        __shared__ float s2[NTHREADS / 32];
        if ((tid & 31) == 0) s2[tid >> 5] = v;
        __syncthreads();
        if (tid == 0) {
            float tot = 0.0f;
            #pragma unroll
            for (int i = 0; i < NTHREADS / 32; i++) tot += s2[i];
            out[0] = -(*weight) * tot * inv_nm1;
            g_next = 0;   // reset for next graph replay
            g_done = 0;
        }
    }
}

extern "C" void kernel_launch(void* const* d_in, const int* in_sizes, int n_in,
                              void* d_out, int out_size) {
    const float* factor = (const float*)d_in[0];
    const float* weight = (const float*)d_in[1];
    float* out = (float*)d_out;

    const int D = 2000;
    const long long total = (long long)in_sizes[0];   // N * D floats
    const long long N = total / D;
    const long long M = (N - 1) * (long long)D;       // product count
    const long long Mv = M / 4;                       // float4 pairs
    const long long Nf4 = total / 4;                  // float4 in array
    const int Dv = D / 4;
    const int nchunks = (int)((Mv + STEP_F4 - 1) / STEP_F4);

    cudaFuncSetAttribute(shifted_dot_tma,
                         cudaFuncAttributeMaxDynamicSharedMemorySize, SMEM_SZ);

    shifted_dot_tma<<<NBLOCKS, NTHREADS, SMEM_SZ>>>(
        (const float4*)factor, Mv, Nf4, Dv, nchunks, weight, out,
        1.0f / (float)(N - 1));
}

// round 10
// speedup vs baseline: 1.0192x; 1.0192x over previous
#include <cuda_runtime.h>
#include <cstdint>

// out = -weight * sum_{k=0}^{M-1} f[k]*f[k+D] / (N-1),  M = (N-1)*D, D=2000.
//
// R8 base (persistent grid, dynamic 32KB-chunk stealing, per-thread register
// accumulators, ONE __syncthreads per chunk) + L2 PREFETCH of the NEXT chunk
// while computing the current one. prefetch.global.L2 has no destination
// register and no scoreboard, so the DRAM request stream is decoupled from
// FFMA consumption; the compute loads then hit L2 (~250cyc) and are easily
// hidden by 48 warps/SM. Prefetch-ahead footprint ~36MB << 126MB L2.

#define NBLOCKS 1216
#define NTHREADS 256
#define CHUNK 2048            // float4 per chunk = 32KB payload
#define HALO_F4 512           // >= Dv=500; prefetch covers payload+halo
#define PF_LINES (((CHUNK + HALO_F4) * 16 + 127) / 128)   // 320 lines

__device__ float g_partials[NBLOCKS];
__device__ unsigned int g_next = 0;
__device__ unsigned int g_done = 0;

__global__ __launch_bounds__(NTHREADS)
void shifted_dot_pf(const float4* __restrict__ in4, long long Mv,
                    long long Nf4, int Dv, int nchunks,
                    const float* __restrict__ weight, float* __restrict__ out,
                    float inv_nm1) {
    __shared__ unsigned int s_next[2];

    if (threadIdx.x == 0) s_next[0] = atomicAdd(&g_next, 1u);
    __syncthreads();
    int par = 0;
    unsigned int c = s_next[0];

    const char* bytes = (const char*)in4;
    const long long nbytes = Nf4 * 16;

    float acc = 0.0f;

    while (c < (unsigned int)nchunks) {
        // Publish next chunk id to the whole block (one barrier per chunk).
        if (threadIdx.x == 0) s_next[par ^ 1] = atomicAdd(&g_next, 1u);
        __syncthreads();
        const unsigned int cn = s_next[par ^ 1];

        // Prefetch next chunk (payload + halo) into L2: dense, dependency-free
        // DRAM request burst, issued while current chunk computes.
        if (cn < (unsigned int)nchunks) {
            const long long pbeg = (long long)cn * CHUNK * 16;
            #pragma unroll
            for (int r = 0; r < 2; r++) {
                int line = threadIdx.x + r * NTHREADS;
                long long addr = pbeg + (long long)line * 128;
                if (line < PF_LINES && addr < nbytes) {
                    asm volatile("prefetch.global.L2 [%0];"
                                 :: "l"(bytes + addr));
                }
            }
        }

        // Compute current chunk (loads mostly L2 hits after prefetch).
        const long long beg = (long long)c * CHUNK;
        long long end = beg + CHUNK;
        if (end > Mv) end = Mv;

        long long t = beg + threadIdx.x;
        for (; t + 3 * NTHREADS < end; t += 4 * NTHREADS) {
            float4 a0 = in4[t];
            float4 a1 = in4[t + NTHREADS];
            float4 a2 = in4[t + 2 * NTHREADS];
            float4 a3 = in4[t + 3 * NTHREADS];
            float4 b0 = in4[t + Dv];
            float4 b1 = in4[t + NTHREADS + Dv];
            float4 b2 = in4[t + 2 * NTHREADS + Dv];
            float4 b3 = in4[t + 3 * NTHREADS + Dv];
            acc += a0.x * b0.x + a0.y * b0.y + a0.z * b0.z + a0.w * b0.w;
            acc += a1.x * b1.x + a1.y * b1.y + a1.z * b1.z + a1.w * b1.w;
            acc += a2.x * b2.x + a2.y * b2.y + a2.z * b2.z + a2.w * b2.w;
            acc += a3.x * b3.x + a3.y * b3.y + a3.z * b3.z + a3.w * b3.w;
        }
        for (; t < end; t += NTHREADS) {
            float4 a = in4[t];
            float4 b = in4[t + Dv];
            acc += a.x * b.x + a.y * b.y + a.z * b.z + a.w * b.w;
        }

        par ^= 1;
        c = cn;
    }

    // One block reduction at the very end.
    #pragma unroll
    for (int o = 16; o > 0; o >>= 1)
        acc += __shfl_xor_sync(0xffffffff, acc, o);

    __shared__ float s[NTHREADS / 32];
    if ((threadIdx.x & 31) == 0) s[threadIdx.x >> 5] = acc;
    __syncthreads();

    __shared__ bool is_last;
    if (threadIdx.x == 0) {
        float v = 0.0f;
        #pragma unroll
        for (int i = 0; i < NTHREADS / 32; i++) v += s[i];
        g_partials[blockIdx.x] = v;
        __threadfence();
        unsigned int old = atomicAdd(&g_done, 1u);
        is_last = (old == gridDim.x - 1);
    }
    __syncthreads();

    if (is_last) {
        const volatile float* p = g_partials;
        float v = 0.0f;
        for (int i = threadIdx.x; i < (int)gridDim.x; i += NTHREADS)
            v += p[i];
        #pragma unroll
        for (int o = 16; o > 0; o >>= 1)
            v += __shfl_xor_sync(0xffffffff, v, o);

        __shared__ float s2[NTHREADS / 32];
        if ((threadIdx.x & 31) == 0) s2[threadIdx.x >> 5] = v;
        __syncthreads();
        if (threadIdx.x == 0) {
            float tot = 0.0f;
            #pragma unroll
            for (int i = 0; i < NTHREADS / 32; i++) tot += s2[i];
            out[0] = -(*weight) * tot * inv_nm1;
            g_next = 0;   // reset for next graph replay
            g_done = 0;
        }
    }
}

extern "C" void kernel_launch(void* const* d_in, const int* in_sizes, int n_in,
                              void* d_out, int out_size) {
    const float* factor = (const float*)d_in[0];
    const float* weight = (const float*)d_in[1];
    float* out = (float*)d_out;

    const int D = 2000;
    const long long total = (long long)in_sizes[0];   // N * D floats
    const long long N = total / D;
    const long long M = (N - 1) * (long long)D;       // divisible by 4
    const long long Mv = M / 4;                       // float4 pair count
    const long long Nf4 = total / 4;                  // float4 in array
    const int Dv = D / 4;
    const int nchunks = (int)((Mv + CHUNK - 1) / CHUNK);

    shifted_dot_pf<<<NBLOCKS, NTHREADS>>>(
        (const float4*)factor, Mv, Nf4, Dv, nchunks, weight, out,
        1.0f / (float)(N - 1));
}

// round 11
// speedup vs baseline: 1.0212x; 1.0019x over previous
#include <cuda_runtime.h>

// out = -weight * sum_{k=0}^{M-1} f[k]*f[k+D] / (N-1),  M = (N-1)*D, D=2000.
//
// R8 structure (persistent grid, dynamic 32KB-chunk stealing, per-thread
// register accumulators carried across chunks, ONE __syncthreads per chunk)
// with FORCED 8 blocks/SM residency: __launch_bounds__(256,8) pins regs<=32
// (unroll cut 4->2 so no spills), raising warps/SM 48->64. DRAM% has tracked
// warps/SM all session (32w:73%, 48w:80.5%); more warps interleave the
// per-warp load-burst gaps into a smoother DRAM request stream.

#define NBLOCKS 1216
#define NTHREADS 256
#define CHUNK 2048            // float4 per chunk = 32KB

__device__ float g_partials[NBLOCKS];
__device__ unsigned int g_next = 0;
__device__ unsigned int g_done = 0;

__global__ __launch_bounds__(NTHREADS, 8)
void shifted_dot_occ(const float4* __restrict__ in4, long long Mv, int Dv,
                     int nchunks,
                     const float* __restrict__ weight, float* __restrict__ out,
                     float inv_nm1) {
    __shared__ unsigned int s_next[2];

    if (threadIdx.x == 0) s_next[0] = atomicAdd(&g_next, 1u);
    __syncthreads();
    int par = 0;
    unsigned int c = s_next[0];

    float acc = 0.0f;

    while (c < (unsigned int)nchunks) {
        // Prefetch next chunk id; hides atomic latency behind the streaming.
        if (threadIdx.x == 0) s_next[par ^ 1] = atomicAdd(&g_next, 1u);

        const long long beg = (long long)c * CHUNK;
        long long end = beg + CHUNK;
        if (end > Mv) end = Mv;

        long long t = beg + threadIdx.x;
        // unroll 2: 4 float4 in flight (16 data regs) -> fits 32-reg budget.
        for (; t + NTHREADS < end; t += 2 * NTHREADS) {
            float4 a0 = in4[t];
            float4 a1 = in4[t + NTHREADS];
            float4 b0 = in4[t + Dv];
            float4 b1 = in4[t + NTHREADS + Dv];
            acc += a0.x * b0.x + a0.y * b0.y + a0.z * b0.z + a0.w * b0.w;
            acc += a1.x * b1.x + a1.y * b1.y + a1.z * b1.z + a1.w * b1.w;
        }
        for (; t < end; t += NTHREADS) {
            float4 a = in4[t];
            float4 b = in4[t + Dv];
            acc += a.x * b.x + a.y * b.y + a.z * b.z + a.w * b.w;
        }

        __syncthreads();        // id visibility only — no data drain
        par ^= 1;
        c = s_next[par];
    }

    // One block reduction at the very end.
    #pragma unroll
    for (int o = 16; o > 0; o >>= 1)
        acc += __shfl_xor_sync(0xffffffff, acc, o);

    __shared__ float s[NTHREADS / 32];
    if ((threadIdx.x & 31) == 0) s[threadIdx.x >> 5] = acc;
    __syncthreads();

    __shared__ bool is_last;
    if (threadIdx.x == 0) {
        float v = 0.0f;
        #pragma unroll
        for (int i = 0; i < NTHREADS / 32; i++) v += s[i];
        g_partials[blockIdx.x] = v;
        __threadfence();
        unsigned int old = atomicAdd(&g_done, 1u);
        is_last = (old == gridDim.x - 1);
    }
    __syncthreads();

    if (is_last) {
        const volatile float* p = g_partials;
        float v = 0.0f;
        for (int i = threadIdx.x; i < (int)gridDim.x; i += NTHREADS)
            v += p[i];
        #pragma unroll
        for (int o = 16; o > 0; o >>= 1)
            v += __shfl_xor_sync(0xffffffff, v, o);

        __shared__ float s2[NTHREADS / 32];
        if ((threadIdx.x & 31) == 0) s2[threadIdx.x >> 5] = v;
        __syncthreads();
        if (threadIdx.x == 0) {
            float tot = 0.0f;
            #pragma unroll
            for (int i = 0; i < NTHREADS / 32; i++) tot += s2[i];
            out[0] = -(*weight) * tot * inv_nm1;
            g_next = 0;   // reset for next graph replay
            g_done = 0;
        }
    }
}

extern "C" void kernel_launch(void* const* d_in, const int* in_sizes, int n_in,
                              void* d_out, int out_size) {
    const float* factor = (const float*)d_in[0];
    const float* weight = (const float*)d_in[1];
    float* out = (float*)d_out;

    const int D = 2000;
    const long long total = (long long)in_sizes[0];   // N * D
    const long long N = total / D;
    const long long M = (N - 1) * (long long)D;       // divisible by 4
    const long long Mv = M / 4;                       // float4 count
    const int Dv = D / 4;
    const int nchunks = (int)((Mv + CHUNK - 1) / CHUNK);

    shifted_dot_occ<<<NBLOCKS, NTHREADS>>>(
        (const float4*)factor, Mv, Dv, nchunks, weight, out,
        1.0f / (float)(N - 1));
}

// round 12
// speedup vs baseline: 1.0293x; 1.0080x over previous
#include <cuda_runtime.h>

// out = -weight * sum_{k=0}^{M-1} f[k]*f[k+D] / (N-1),  M = (N-1)*D, D=2000.
//
// R8 base (persistent 1216-block grid, dynamic chunk stealing, per-thread
// register accumulators carried across chunks, ONE __syncthreads per chunk)
// + TWO-TIER POOL to kill the end-of-pool stagger:
//   - coarse region: 32KB chunks (halo 25% -> L2 ~1.25x) covering ~92% of data
//   - fine region:   8KB chunks (only ~8% of data; +~8% L2 total) at the end
// One shared counter; id < n_coarse -> coarse chunk, else fine chunk.
// Blocks finishing early drain 1.5us fine chunks while stragglers complete
// their last 6us coarse chunk -> finish spread ~1.5us instead of ~6us.

#define NBLOCKS 1216
#define NTHREADS 256
#define CHUNK 2048            // coarse: float4 per chunk = 32KB
#define FINE 512              // fine:   float4 per chunk = 8KB

__device__ float g_partials[NBLOCKS];
__device__ unsigned int g_next = 0;
__device__ unsigned int g_done = 0;

__global__ __launch_bounds__(NTHREADS)
void shifted_dot_2tier(const float4* __restrict__ in4, long long Mv, int Dv,
                       int n_coarse, int nchunks, long long fine_base,
                       const float* __restrict__ weight, float* __restrict__ out,
                       float inv_nm1) {
    __shared__ unsigned int s_next[2];

    if (threadIdx.x == 0) s_next[0] = atomicAdd(&g_next, 1u);
    __syncthreads();
    int par = 0;
    unsigned int c = s_next[0];

    float acc = 0.0f;

    while (c < (unsigned int)nchunks) {
        // Prefetch next chunk id; latency hidden behind the streaming.
        if (threadIdx.x == 0) s_next[par ^ 1] = atomicAdd(&g_next, 1u);

        if (c < (unsigned int)n_coarse) {
            // coarse chunk: always full 2048 float4
            const long long beg = (long long)c * CHUNK;
            long long t = beg + threadIdx.x;
            #pragma unroll
            for (int g = 0; g < CHUNK / (4 * NTHREADS); g++) {
                float4 a0 = in4[t];
                float4 a1 = in4[t + NTHREADS];
                float4 a2 = in4[t + 2 * NTHREADS];
                float4 a3 = in4[t + 3 * NTHREADS];
                float4 b0 = in4[t + Dv];
                float4 b1 = in4[t + NTHREADS + Dv];
                float4 b2 = in4[t + 2 * NTHREADS + Dv];
                float4 b3 = in4[t + 3 * NTHREADS + Dv];
                acc += a0.x * b0.x + a0.y * b0.y + a0.z * b0.z + a0.w * b0.w;
                acc += a1.x * b1.x + a1.y * b1.y + a1.z * b1.z + a1.w * b1.w;
                acc += a2.x * b2.x + a2.y * b2.y + a2.z * b2.z + a2.w * b2.w;
                acc += a3.x * b3.x + a3.y * b3.y + a3.z * b3.z + a3.w * b3.w;
                t += 4 * NTHREADS;
            }
        } else {
            // fine chunk: 512 float4 (last one may be partial)
            const long long beg = fine_base
                + (long long)(c - (unsigned int)n_coarse) * FINE;
            long long end = beg + FINE;
            if (end > Mv) end = Mv;
            for (long long t = beg + threadIdx.x; t < end; t += NTHREADS) {
                float4 a = in4[t];
                float4 b = in4[t + Dv];
                acc += a.x * b.x + a.y * b.y + a.z * b.z + a.w * b.w;
            }
        }

        __syncthreads();        // id visibility only — no data drain
        par ^= 1;
        c = s_next[par];
    }

    // One block reduction at the very end.
    #pragma unroll
    for (int o = 16; o > 0; o >>= 1)
        acc += __shfl_xor_sync(0xffffffff, acc, o);

    __shared__ float s[NTHREADS / 32];
    if ((threadIdx.x & 31) == 0) s[threadIdx.x >> 5] = acc;
    __syncthreads();

    __shared__ bool is_last;
    if (threadIdx.x == 0) {
        float v = 0.0f;
        #pragma unroll
        for (int i = 0; i < NTHREADS / 32; i++) v += s[i];
        g_partials[blockIdx.x] = v;
        __threadfence();
        unsigned int old = atomicAdd(&g_done, 1u);
        is_last = (old == gridDim.x - 1);
    }
    __syncthreads();

    if (is_last) {
        const volatile float* p = g_partials;
        float v = 0.0f;
        for (int i = threadIdx.x; i < (int)gridDim.x; i += NTHREADS)
            v += p[i];
        #pragma unroll
        for (int o = 16; o > 0; o >>= 1)
            v += __shfl_xor_sync(0xffffffff, v, o);

        __shared__ float s2[NTHREADS / 32];
        if ((threadIdx.x & 31) == 0) s2[threadIdx.x >> 5] = v;
        __syncthreads();
        if (threadIdx.x == 0) {
            float tot = 0.0f;
            #pragma unroll
            for (int i = 0; i < NTHREADS / 32; i++) tot += s2[i];
            out[0] = -(*weight) * tot * inv_nm1;
            g_next = 0;   // reset for next graph replay
            g_done = 0;
        }
    }
}

extern "C" void kernel_launch(void* const* d_in, const int* in_sizes, int n_in,
                              void* d_out, int out_size) {
    const float* factor = (const float*)d_in[0];
    const float* weight = (const float*)d_in[1];
    float* out = (float*)d_out;

    const int D = 2000;
    const long long total = (long long)in_sizes[0];   // N * D
    const long long N = total / D;
    const long long M = (N - 1) * (long long)D;       // divisible by 4
    const long long Mv = M / 4;                       // float4 count
    const int Dv = D / 4;

    // fine region target: ~4 fine chunks per block (~38MB, ~7% of data)
    const long long fine_target = (long long)4 * NBLOCKS * FINE;
    long long coarse_elems = Mv - fine_target;
    if (coarse_elems < 0) coarse_elems = 0;
    const int n_coarse = (int)(coarse_elems / CHUNK);
    const long long fine_base = (long long)n_coarse * CHUNK;
    const int n_fine = (int)((Mv - fine_base + FINE - 1) / FINE);
    const int nchunks = n_coarse + n_fine;

    shifted_dot_2tier<<<NBLOCKS, NTHREADS>>>(
        (const float4*)factor, Mv, Dv, n_coarse, nchunks, fine_base,
        weight, out, 1.0f / (float)(N - 1));
}